// round 10
// baseline (speedup 1.0000x reference)
#include <cuda_runtime.h>
#include <cstdint>

// Problem constants
#define BB   2048
#define HH   2048
#define RNK  64
#define LL   32

#define NKG  16          // split-K groups for GEMM1 (k per block = 128)
#define KCH  (HH / NKG)  // 128
#define KST  64          // K staged per pipeline stage (2 stages per m-chunk)
#define MT   64          // M tile (samples)
#define HT   64          // h tile for GEMM2
#define TPB  256         // proj: 8 warps
#define OTPB 128         // out: 4 warps
#define STZ  68          // stride sample-major z tile  (68 mod 32 == 4)
#define STB  72          // stride k-major v tile       (72 mod 32 == 8)
#define STU  68          // stride n-major u/proj tiles (68 mod 32 == 4)

#define ZW   (MT * STZ)        // words per z stage buffer
#define VW   (KST * STB)       // words per v stage buffer
#define BUFW (ZW + VW)

#define RED_BLOCKS 128         // reduce worker blocks
#define PF_BLOCKS  64          // u-prefetch blocks appended to reduce grid

// Scratch (device globals — no allocations allowed)
__device__ int    g_offsets[LL + 1];
__device__ int    g_sorted[BB];
__device__ float  g_partial[(size_t)NKG * BB * RNK];   // 8 MB, indexed by sorted pos
__device__ float  g_proj[(size_t)BB * RNK];            // indexed by sorted pos

#define MMA_TF32(c0,c1,c2,c3,a0,a1,a2,a3,b0,b1)                         \
    asm("mma.sync.aligned.m16n8k8.row.col.f32.tf32.tf32.f32 "           \
        "{%0,%1,%2,%3}, {%4,%5,%6,%7}, {%8,%9}, {%0,%1,%2,%3};"         \
        : "+f"(c0), "+f"(c1), "+f"(c2), "+f"(c3)                        \
        : "r"(a0), "r"(a1), "r"(a2), "r"(a3), "r"(b0), "r"(b1))

__device__ __forceinline__ void cpa16(uint32_t dst, const void* src, uint32_t sz) {
    asm volatile("cp.async.cg.shared.global [%0], [%1], 16, %2;"
                 :: "r"(dst), "l"(src), "r"(sz));
}
__device__ __forceinline__ void cpa_commit() { asm volatile("cp.async.commit_group;"); }
__device__ __forceinline__ void cpa_wait0()  { asm volatile("cp.async.wait_group 0;"); }
__device__ __forceinline__ void cpa_wait1()  { asm volatile("cp.async.wait_group 1;"); }
__device__ __forceinline__ void l2pf(const void* p) {
    asm volatile("prefetch.global.L2 [%0];" :: "l"(p));
}

// ---------------------------------------------------------------------------
// Kernel 1: block 0 = stable counting sort (deterministic).
//           blocks 1..147 = L2 prefetch of z and v (overlaps the sort).
// ---------------------------------------------------------------------------
__global__ void setup_kernel(const int* __restrict__ ids,
                             const float* __restrict__ z,
                             const float* __restrict__ v) {
    int t = threadIdx.x;

    if (blockIdx.x != 0) {
        // L2 prefetch: z (16MB) + v (16MB), 128B lines, grid-strided
        const int nthr = 147 * 256;
        int pid = (blockIdx.x - 1) * 256 + t;
        const char* zb = (const char*)z;
        const char* vb = (const char*)v;
        const size_t zbytes = (size_t)BB * HH * 4;
        const size_t vbytes = (size_t)LL * HH * RNK * 4;
        for (size_t o = (size_t)pid * 128; o < zbytes; o += (size_t)nthr * 128)
            l2pf(zb + o);
        for (size_t o = (size_t)pid * 128; o < vbytes; o += (size_t)nthr * 128)
            l2pf(vb + o);
        return;
    }

    __shared__ int A[LL * 256];
    __shared__ int S[256];

    #pragma unroll
    for (int l = 0; l < LL; l++) A[l * 256 + t] = 0;
    int seg = t * (BB / 256);
    #pragma unroll
    for (int i = 0; i < BB / 256; i++) {
        int lid = ids[seg + i];
        A[lid * 256 + t]++;
    }
    __syncthreads();

    int base = t * 32;
    int sum = 0;
    #pragma unroll
    for (int j = 0; j < 32; j++) { int x = A[base + j]; A[base + j] = sum; sum += x; }
    S[t] = sum;
    int mysum = sum;
    __syncthreads();
    for (int d = 1; d < 256; d <<= 1) {
        int add = (t >= d) ? S[t - d] : 0;
        __syncthreads();
        S[t] += add;
        __syncthreads();
    }
    int excl = S[t] - mysum;
    #pragma unroll
    for (int j = 0; j < 32; j++) A[base + j] += excl;
    __syncthreads();

    if (t < LL) g_offsets[t] = A[t * 256];
    if (t == 0) g_offsets[LL] = BB;

    #pragma unroll
    for (int i = 0; i < BB / 256; i++) {
        int s = seg + i;
        int lid = ids[s];
        int p = A[lid * 256 + t];
        A[lid * 256 + t] = p + 1;
        g_sorted[p] = s;
    }
}

// ---------------------------------------------------------------------------
// Kernel 2: GEMM1 split-K, tf32 mma, 2-stage cp.async pipeline.
// block = (kg in [0,16), layer); 8 warps; warp = m32 (wm) x n16 (wn).
// it = (m-chunk * 2 + kk), KST=64 per stage, KCH=128 per block.
// partial[kg][p][r] = sum_{k in chunk} v[l][k][r] * z[sorted[p]][k]
// ---------------------------------------------------------------------------
__global__ __launch_bounds__(TPB, 3) void proj_kernel(const float* __restrict__ z,
                                                      const float* __restrict__ v) {
    extern __shared__ __align__(16) uint32_t smem1[];   // 2 x (z[MT][STZ], v[KST][STB])

    int t = threadIdx.x, lane = t & 31, w = t >> 5;
    int gid = lane >> 2, tig = lane & 3;
    int wm = w & 1, wn = w >> 1;
    int kg = blockIdx.x, l = blockIdx.y;

    uint32_t sb = (uint32_t)__cvta_generic_to_shared(smem1);

    int off = g_offsets[l];
    int cnt = g_offsets[l + 1] - off;
    int nm = (cnt + MT - 1) / MT;
    int total = nm * 2;
    if (total == 0) return;

    auto stage = [&](int it) {
        int m0 = (it >> 1) * MT;
        int nc = min(MT, cnt - m0);
        int k0 = kg * KCH + (it & 1) * KST;
        uint32_t zb = sb + (uint32_t)(it & 1) * BUFW * 4;
        uint32_t vb = zb + ZW * 4;
        #pragma unroll
        for (int i = 0; i < (MT * 16) / TPB; i++) {     // 4 iters
            int idx = t + i * TPB;
            int row = idx >> 4, c4 = idx & 15;
            const float* src = z;
            uint32_t szb = 0;
            if (row < nc) {
                int gs = g_sorted[off + m0 + row];
                src = z + (size_t)gs * HH + k0 + c4 * 4;
                szb = 16;
            }
            cpa16(zb + (row * STZ + c4 * 4) * 4, src, szb);
        }
        #pragma unroll
        for (int i = 0; i < (KST * 16) / TPB; i++) {    // 4 iters
            int idx = t + i * TPB;
            int row = idx >> 4, c4 = idx & 15;
            cpa16(vb + (row * STB + c4 * 4) * 4,
                  v + ((size_t)l * HH + k0 + row) * RNK + c4 * 4, 16);
        }
        cpa_commit();
    };

    stage(0);
    if (total > 1) stage(1);

    float acc[2][2][4];
    for (int it = 0; it < total; it++) {
        int kk = it & 1;
        if (kk == 0) {
            #pragma unroll
            for (int mt = 0; mt < 2; mt++)
                #pragma unroll
                for (int j = 0; j < 2; j++)
                    #pragma unroll
                    for (int q = 0; q < 4; q++) acc[mt][j][q] = 0.0f;
        }
        if (it + 2 <= total) cpa_wait1(); else cpa_wait0();
        __syncthreads();

        const uint32_t* zt = smem1 + (it & 1) * BUFW;
        const uint32_t* vt = zt + ZW;

        #pragma unroll
        for (int ks = 0; ks < KST / 8; ks++) {          // 8 iters
            int kb = ks * 8 + tig;
            uint32_t b0[2], b1[2];
            #pragma unroll
            for (int j = 0; j < 2; j++) {
                int n = wn * 16 + j * 8 + gid;
                b0[j] = vt[kb * STB + n];
                b1[j] = vt[(kb + 4) * STB + n];
            }
            #pragma unroll
            for (int mt = 0; mt < 2; mt++) {
                const uint32_t* zr = zt + (wm * 32 + mt * 16 + gid) * STZ;
                uint32_t a0 = zr[kb];
                uint32_t a1 = zr[8 * STZ + kb];
                uint32_t a2 = zr[kb + 4];
                uint32_t a3 = zr[8 * STZ + kb + 4];
                #pragma unroll
                for (int j = 0; j < 2; j++)
                    MMA_TF32(acc[mt][j][0], acc[mt][j][1], acc[mt][j][2], acc[mt][j][3],
                             a0, a1, a2, a3, b0[j], b1[j]);
            }
        }
        __syncthreads();
        if (it + 2 < total) stage(it + 2);

        if (kk == 1) {
            int m0 = (it >> 1) * MT;
            int nc = min(MT, cnt - m0);
            float* pb = g_partial + (size_t)kg * BB * RNK;
            #pragma unroll
            for (int mt = 0; mt < 2; mt++) {
                int rbase = wm * 32 + mt * 16 + gid;
                #pragma unroll
                for (int j = 0; j < 2; j++) {
                    int col = wn * 16 + j * 8 + 2 * tig;
                    if (rbase < nc)
                        *(float2*)&pb[(size_t)(off + m0 + rbase) * RNK + col] =
                            make_float2(acc[mt][j][0], acc[mt][j][1]);
                    if (rbase + 8 < nc)
                        *(float2*)&pb[(size_t)(off + m0 + rbase + 8) * RNK + col] =
                            make_float2(acc[mt][j][2], acc[mt][j][3]);
                }
            }
        }
    }
}

// ---------------------------------------------------------------------------
// Kernel 3: blocks [0,128) = deterministic split-K reduction (16 groups);
//           blocks [128,192) = L2 prefetch of u (overlaps the reduction).
// ---------------------------------------------------------------------------
__global__ void reduce_kernel(const float* __restrict__ u) {
    if (blockIdx.x >= RED_BLOCKS) {
        const int nthr = PF_BLOCKS * 256;
        int pid = (blockIdx.x - RED_BLOCKS) * 256 + threadIdx.x;
        const char* ub = (const char*)u;
        const size_t ubytes = (size_t)LL * HH * RNK * 4;
        for (size_t o = (size_t)pid * 128; o < ubytes; o += (size_t)nthr * 128)
            l2pf(ub + o);
        return;
    }
    int i = blockIdx.x * blockDim.x + threadIdx.x;
    const int n4 = BB * RNK / 4;
    if (i >= n4) return;
    const float4* p = (const float4*)g_partial;
    float4 s = p[i];
    #pragma unroll
    for (int kc = 1; kc < NKG; kc++) {
        float4 q = p[(size_t)kc * n4 + i];
        s.x += q.x; s.y += q.y; s.z += q.z; s.w += q.w;
    }
    ((float4*)g_proj)[i] = s;
}

// ---------------------------------------------------------------------------
// Kernel 4: GEMM2 + epilogue. 64x64 tiles, 4 warps (warp = m32 x n32),
// 1024 blocks. All operands L2-resident after prefetch. z-epilogue in regs.
// ---------------------------------------------------------------------------
__global__ __launch_bounds__(OTPB, 6) void out_kernel(const float* __restrict__ z,
                                                      const float* __restrict__ u,
                                                      float* __restrict__ out) {
    extern __shared__ __align__(16) uint32_t smem2[];
    uint32_t* su = smem2;                  // [HT][STU]  u tile    17.4 KB
    uint32_t* sp = smem2 + HT * STU;       // [MT][STU]  proj tile 17.4 KB

    int t = threadIdx.x, lane = t & 31, w = t >> 5;
    int gid = lane >> 2, tig = lane & 3;
    int wm = w & 1, wn = w >> 1;           // 4 warps: m32 x n32
    int hb = blockIdx.x, l = blockIdx.y;
    int h0 = hb * HT;

    uint32_t su_b = (uint32_t)__cvta_generic_to_shared(su);
    uint32_t sp_b = (uint32_t)__cvta_generic_to_shared(sp);

    int off = g_offsets[l];
    int cnt = g_offsets[l + 1] - off;
    if (cnt == 0) return;

    // stage u tile (once): su[h][r], 64 rows x 16 float4
    #pragma unroll
    for (int i = 0; i < (HT * 16) / OTPB; i++) {            // 8 iters
        int idx = t + i * OTPB;
        int row = idx >> 4, c4 = idx & 15;
        cpa16(su_b + (row * STU + c4 * 4) * 4,
              u + ((size_t)l * HH + h0 + row) * RNK + c4 * 4, 16);
    }
    cpa_commit();

    for (int m0 = 0; m0 < cnt; m0 += MT) {
        int nc = min(MT, cnt - m0);
        __syncthreads();   // previous-iteration sp consumed
        #pragma unroll
        for (int i = 0; i < (MT * 16) / OTPB; i++) {        // 8 iters
            int idx = t + i * OTPB;
            int row = idx >> 4, c4 = idx & 15;
            const float* src = g_proj;
            uint32_t szb = 0;
            if (row < nc) {
                src = g_proj + (size_t)(off + m0 + row) * RNK + c4 * 4;
                szb = 16;
            }
            cpa16(sp_b + (row * STU + c4 * 4) * 4, src, szb);
        }
        cpa_commit();
        cpa_wait0();
        __syncthreads();

        // prefetch epilogue z into registers (overlaps with MMA below)
        int    gsr[2][2];
        float2 zpre[2][2][4];
        #pragma unroll
        for (int mt = 0; mt < 2; mt++)
            #pragma unroll
            for (int half = 0; half < 2; half++) {
                int rr = wm * 32 + mt * 16 + gid + half * 8;
                int rid = (rr < nc) ? rr : 0;
                int gs = g_sorted[off + m0 + rid];
                gsr[mt][half] = gs;
                const float* zrow = z + (size_t)gs * HH + h0;
                #pragma unroll
                for (int j = 0; j < 4; j++)
                    zpre[mt][half][j] = *(const float2*)&zrow[wn * 32 + j * 8 + 2 * tig];
            }

        float acc[2][4][4];
        #pragma unroll
        for (int mt = 0; mt < 2; mt++)
            #pragma unroll
            for (int j = 0; j < 4; j++)
                #pragma unroll
                for (int q = 0; q < 4; q++) acc[mt][j][q] = 0.0f;

        #pragma unroll
        for (int ks = 0; ks < 8; ks++) {
            int kb = ks * 8 + tig;
            uint32_t b0[4], b1[4];
            #pragma unroll
            for (int j = 0; j < 4; j++) {
                int n = wn * 32 + j * 8 + gid;
                b0[j] = su[n * STU + kb];
                b1[j] = su[n * STU + kb + 4];
            }
            #pragma unroll
            for (int mt = 0; mt < 2; mt++) {
                const uint32_t* spr = sp + (wm * 32 + mt * 16 + gid) * STU;
                uint32_t a0 = spr[kb];
                uint32_t a1 = spr[8 * STU + kb];
                uint32_t a2 = spr[kb + 4];
                uint32_t a3 = spr[8 * STU + kb + 4];
                #pragma unroll
                for (int j = 0; j < 4; j++)
                    MMA_TF32(acc[mt][j][0], acc[mt][j][1], acc[mt][j][2], acc[mt][j][3],
                             a0, a1, a2, a3, b0[j], b1[j]);
            }
        }

        // epilogue: out = z(regs) + delta
        #pragma unroll
        for (int mt = 0; mt < 2; mt++) {
            #pragma unroll
            for (int half = 0; half < 2; half++) {
                int rr = wm * 32 + mt * 16 + gid + half * 8;
                if (rr < nc) {
                    float* orow = out + (size_t)gsr[mt][half] * HH + h0;
                    #pragma unroll
                    for (int j = 0; j < 4; j++) {
                        int col = wn * 32 + j * 8 + 2 * tig;
                        float2 zz = zpre[mt][half][j];
                        *(float2*)&orow[col] = make_float2(zz.x + acc[mt][j][half * 2 + 0],
                                                           zz.y + acc[mt][j][half * 2 + 1]);
                    }
                }
            }
        }
    }
}

// ---------------------------------------------------------------------------
extern "C" void kernel_launch(void* const* d_in, const int* in_sizes, int n_in,
                              void* d_out, int out_size) {
    const float* z   = (const float*)d_in[0];
    const int*   ids = (const int*)  d_in[1];
    const float* u   = (const float*)d_in[2];
    const float* v   = (const float*)d_in[3];
    float*       out = (float*)d_out;

    const int proj_smem = 2 * BUFW * 4;                  // 71.7 KB
    const int out_smem  = (HT * STU + MT * STU) * 4;     // 34.8 KB
    cudaFuncSetAttribute(proj_kernel, cudaFuncAttributeMaxDynamicSharedMemorySize, proj_smem);
    cudaFuncSetAttribute(out_kernel,  cudaFuncAttributeMaxDynamicSharedMemorySize, out_smem);

    setup_kernel<<<148, 256>>>(ids, z, v);
    proj_kernel<<<dim3(NKG, LL), TPB, proj_smem>>>(z, v);
    reduce_kernel<<<RED_BLOCKS + PF_BLOCKS, 256>>>(u);
    out_kernel<<<dim3(HH / HT, LL), OTPB, out_smem>>>(z, u, out);
}

// round 11
// speedup vs baseline: 1.4341x; 1.4341x over previous
#include <cuda_runtime.h>
#include <cstdint>

// Problem constants
#define BB   2048
#define HH   2048
#define RNK  64
#define LL   32

#define NKG  32          // split-K groups for GEMM1 (k per block = 64)
#define KCH  64
#define MT   64          // M tile (samples)
#define HT   64          // h tile for GEMM2
#define TPB  256         // 8 warps everywhere
#define STZ  68          // sample-major tiles stride (68 mod 32 == 4)
#define STB  72          // k-major v tile stride     (72 mod 32 == 8)
#define STU  68          // n-major u/proj stride     (68 mod 32 == 4)

#define PROJ_BLOCKS (NKG * LL)       // 1024
#define OUT_BLOCKS  ((HH / HT) * LL) // 1024

// Scratch (device globals — no allocations allowed)
__device__ int    g_offsets[LL + 1];
__device__ int    g_sorted[BB];
__device__ float  g_partial[(size_t)NKG * BB * RNK];   // 16 MB, by sorted pos
__device__ float  g_proj[(size_t)BB * RNK];            // by sorted pos
__device__ int    g_done[LL];
__device__ int    g_flag[LL];

#define MMA_TF32(c0,c1,c2,c3,a0,a1,a2,a3,b0,b1)                         \
    asm("mma.sync.aligned.m16n8k8.row.col.f32.tf32.tf32.f32 "           \
        "{%0,%1,%2,%3}, {%4,%5,%6,%7}, {%8,%9}, {%0,%1,%2,%3};"         \
        : "+f"(c0), "+f"(c1), "+f"(c2), "+f"(c3)                        \
        : "r"(a0), "r"(a1), "r"(a2), "r"(a3), "r"(b0), "r"(b1))

__device__ __forceinline__ void cpa16(uint32_t dst, const void* src, uint32_t sz) {
    asm volatile("cp.async.cg.shared.global [%0], [%1], 16, %2;"
                 :: "r"(dst), "l"(src), "r"(sz));
}
__device__ __forceinline__ void cpa_commit_wait() {
    asm volatile("cp.async.commit_group;");
    asm volatile("cp.async.wait_group 0;");
}

// ---------------------------------------------------------------------------
// Kernel 1: stable counting sort by layer id + zero flags (deterministic).
// ---------------------------------------------------------------------------
__global__ void setup_kernel(const int* __restrict__ ids) {
    __shared__ int A[LL * 256];
    __shared__ int S[256];
    int t = threadIdx.x;

    if (t < LL) { g_done[t] = 0; g_flag[t] = 0; }

    #pragma unroll
    for (int l = 0; l < LL; l++) A[l * 256 + t] = 0;
    int seg = t * (BB / 256);
    #pragma unroll
    for (int i = 0; i < BB / 256; i++) {
        int lid = ids[seg + i];
        A[lid * 256 + t]++;
    }
    __syncthreads();

    int base = t * 32;
    int sum = 0;
    #pragma unroll
    for (int j = 0; j < 32; j++) { int x = A[base + j]; A[base + j] = sum; sum += x; }
    S[t] = sum;
    int mysum = sum;
    __syncthreads();
    for (int d = 1; d < 256; d <<= 1) {
        int add = (t >= d) ? S[t - d] : 0;
        __syncthreads();
        S[t] += add;
        __syncthreads();
    }
    int excl = S[t] - mysum;
    #pragma unroll
    for (int j = 0; j < 32; j++) A[base + j] += excl;
    __syncthreads();

    if (t < LL) g_offsets[t] = A[t * 256];
    if (t == 0) g_offsets[LL] = BB;

    #pragma unroll
    for (int i = 0; i < BB / 256; i++) {
        int s = seg + i;
        int lid = ids[s];
        int p = A[lid * 256 + t];
        A[lid * 256 + t] = p + 1;
        g_sorted[p] = s;
    }
}

// ---------------------------------------------------------------------------
// Kernel 2: FUSED proj + per-layer reduce + out, overlapped via layer flags.
//   bid in [0, 1024):      proj block  (l = bid/32, kg = bid%32)
//   bid in [1024, 2048):   out block   (l = (bid-1024)/32, hb = (bid-1024)%32)
// Proj blocks never wait; out blocks spin on g_flag[l] (set by the layer's
// last proj block after it performs the deterministic split-K reduction).
// ---------------------------------------------------------------------------
__global__ __launch_bounds__(TPB) void fused_kernel(const float* __restrict__ z,
                                                    const float* __restrict__ v,
                                                    const float* __restrict__ u,
                                                    float* __restrict__ out) {
    extern __shared__ __align__(16) uint32_t smem[];
    __shared__ int s_last;

    int t = threadIdx.x, lane = t & 31, w = t >> 5;
    int gid = lane >> 2, tig = lane & 3;
    int wm = w & 1, wn = w >> 1;           // 8 warps: m32 x n16
    int bid = blockIdx.x;

    if (bid < PROJ_BLOCKS) {
        // ================= PROJ =================
        int l = bid >> 5, kg = bid & 31;
        int k0 = kg * KCH;
        uint32_t* sz = smem;               // [MT][STZ]  17.4 KB
        uint32_t* sv = smem + MT * STZ;    // [KCH][STB] 18.4 KB
        uint32_t sz_b = (uint32_t)__cvta_generic_to_shared(sz);
        uint32_t sv_b = (uint32_t)__cvta_generic_to_shared(sv);

        int off = g_offsets[l];
        int cnt = g_offsets[l + 1] - off;

        for (int m0 = 0; m0 < cnt; m0 += MT) {
            int nc = min(MT, cnt - m0);
            __syncthreads();   // smem free from previous iteration
            // stage z tile: 64 samples x 64 k (zero-fill pad rows)
            #pragma unroll
            for (int i = 0; i < (MT * 16) / TPB; i++) {     // 4 iters
                int idx = t + i * TPB;
                int row = idx >> 4, c4 = idx & 15;
                const float* src = z;
                uint32_t szb = 0;
                if (row < nc) {
                    int gs = g_sorted[off + m0 + row];
                    src = z + (size_t)gs * HH + k0 + c4 * 4;
                    szb = 16;
                }
                cpa16(sz_b + (row * STZ + c4 * 4) * 4, src, szb);
            }
            // stage v tile: 64 k-rows x 64 r
            #pragma unroll
            for (int i = 0; i < (KCH * 16) / TPB; i++) {    // 4 iters
                int idx = t + i * TPB;
                int row = idx >> 4, c4 = idx & 15;
                cpa16(sv_b + (row * STB + c4 * 4) * 4,
                      v + ((size_t)l * HH + k0 + row) * RNK + c4 * 4, 16);
            }
            cpa_commit_wait();
            __syncthreads();

            float acc[2][2][4];
            #pragma unroll
            for (int mt = 0; mt < 2; mt++)
                #pragma unroll
                for (int j = 0; j < 2; j++)
                    #pragma unroll
                    for (int q = 0; q < 4; q++) acc[mt][j][q] = 0.0f;

            #pragma unroll
            for (int ks = 0; ks < KCH / 8; ks++) {          // 8 iters
                int kb = ks * 8 + tig;
                uint32_t b0[2], b1[2];
                #pragma unroll
                for (int j = 0; j < 2; j++) {
                    int n = wn * 16 + j * 8 + gid;
                    b0[j] = sv[kb * STB + n];
                    b1[j] = sv[(kb + 4) * STB + n];
                }
                #pragma unroll
                for (int mt = 0; mt < 2; mt++) {
                    const uint32_t* zr = sz + (wm * 32 + mt * 16 + gid) * STZ;
                    uint32_t a0 = zr[kb];
                    uint32_t a1 = zr[8 * STZ + kb];
                    uint32_t a2 = zr[kb + 4];
                    uint32_t a3 = zr[8 * STZ + kb + 4];
                    #pragma unroll
                    for (int j = 0; j < 2; j++)
                        MMA_TF32(acc[mt][j][0], acc[mt][j][1], acc[mt][j][2], acc[mt][j][3],
                                 a0, a1, a2, a3, b0[j], b1[j]);
                }
            }

            float* pb = g_partial + (size_t)kg * BB * RNK;
            #pragma unroll
            for (int mt = 0; mt < 2; mt++) {
                int rbase = wm * 32 + mt * 16 + gid;
                #pragma unroll
                for (int j = 0; j < 2; j++) {
                    int col = wn * 16 + j * 8 + 2 * tig;
                    if (rbase < nc)
                        *(float2*)&pb[(size_t)(off + m0 + rbase) * RNK + col] =
                            make_float2(acc[mt][j][0], acc[mt][j][1]);
                    if (rbase + 8 < nc)
                        *(float2*)&pb[(size_t)(off + m0 + rbase + 8) * RNK + col] =
                            make_float2(acc[mt][j][2], acc[mt][j][3]);
                }
            }
        }

        // signal + last block performs the layer reduction
        __threadfence();
        if (t == 0) s_last = (atomicAdd(&g_done[l], 1) == NKG - 1) ? 1 : 0;
        __syncthreads();
        if (s_last) {
            const int n4 = cnt * (RNK / 4);
            const int base4 = off * (RNK / 4);
            const float4* pp = (const float4*)g_partial;
            const int stride4 = BB * RNK / 4;
            for (int i = t; i < n4; i += TPB) {
                float4 s = __ldcg(pp + base4 + i);
                #pragma unroll
                for (int kc = 1; kc < NKG; kc++) {
                    float4 q = __ldcg(pp + (size_t)kc * stride4 + base4 + i);
                    s.x += q.x; s.y += q.y; s.z += q.z; s.w += q.w;
                }
                ((float4*)g_proj)[base4 + i] = s;
            }
            __threadfence();
            __syncthreads();
            if (t == 0) atomicExch(&g_flag[l], 1);
        }
        return;
    }

    // ================= OUT =================
    {
        int idx = bid - PROJ_BLOCKS;
        int l = idx >> 5, hb = idx & 31;
        int h0 = hb * HT;
        uint32_t* su = smem;               // [HT][STU]  17.4 KB
        uint32_t* sp = smem + HT * STU;    // [MT][STU]  17.4 KB
        uint32_t su_b = (uint32_t)__cvta_generic_to_shared(su);
        uint32_t sp_b = (uint32_t)__cvta_generic_to_shared(sp);

        int off = g_offsets[l];
        int cnt = g_offsets[l + 1] - off;
        if (cnt == 0) return;

        // stage u tile while waiting is NOT safe (no dependency) — u is
        // independent of proj, so stage it first, then spin.
        #pragma unroll
        for (int i = 0; i < (HT * 16) / TPB; i++) {         // 4 iters
            int idxx = t + i * TPB;
            int row = idxx >> 4, c4 = idxx & 15;
            cpa16(su_b + (row * STU + c4 * 4) * 4,
                  u + ((size_t)l * HH + h0 + row) * RNK + c4 * 4, 16);
        }
        asm volatile("cp.async.commit_group;");

        // wait for this layer's proj+reduce
        if (t == 0) {
            while (atomicAdd(&g_flag[l], 0) == 0) __nanosleep(128);
        }
        __syncthreads();
        __threadfence();

        for (int m0 = 0; m0 < cnt; m0 += MT) {
            int nc = min(MT, cnt - m0);
            if (m0 > 0) __syncthreads();
            #pragma unroll
            for (int i = 0; i < (MT * 16) / TPB; i++) {     // 4 iters
                int idxx = t + i * TPB;
                int row = idxx >> 4, c4 = idxx & 15;
                const float* src = g_proj;
                uint32_t szb = 0;
                if (row < nc) {
                    src = g_proj + (size_t)(off + m0 + row) * RNK + c4 * 4;
                    szb = 16;
                }
                cpa16(sp_b + (row * STU + c4 * 4) * 4, src, szb);
            }
            cpa_commit_wait();   // also covers u on first iteration
            __syncthreads();

            // prefetch epilogue z into registers (overlaps MMA)
            int    gsr[2][2];
            float2 zpre[2][2][2];
            #pragma unroll
            for (int mt = 0; mt < 2; mt++)
                #pragma unroll
                for (int half = 0; half < 2; half++) {
                    int rr = wm * 32 + mt * 16 + gid + half * 8;
                    int rid = (rr < nc) ? rr : 0;
                    int gs = g_sorted[off + m0 + rid];
                    gsr[mt][half] = gs;
                    const float* zrow = z + (size_t)gs * HH + h0;
                    #pragma unroll
                    for (int j = 0; j < 2; j++)
                        zpre[mt][half][j] = *(const float2*)&zrow[wn * 16 + j * 8 + 2 * tig];
                }

            float acc[2][2][4];
            #pragma unroll
            for (int mt = 0; mt < 2; mt++)
                #pragma unroll
                for (int j = 0; j < 2; j++)
                    #pragma unroll
                    for (int q = 0; q < 4; q++) acc[mt][j][q] = 0.0f;

            #pragma unroll
            for (int ks = 0; ks < 8; ks++) {
                int kb = ks * 8 + tig;
                uint32_t b0[2], b1[2];
                #pragma unroll
                for (int j = 0; j < 2; j++) {
                    int n = wn * 16 + j * 8 + gid;
                    b0[j] = su[n * STU + kb];
                    b1[j] = su[n * STU + kb + 4];
                }
                #pragma unroll
                for (int mt = 0; mt < 2; mt++) {
                    const uint32_t* spr = sp + (wm * 32 + mt * 16 + gid) * STU;
                    uint32_t a0 = spr[kb];
                    uint32_t a1 = spr[8 * STU + kb];
                    uint32_t a2 = spr[kb + 4];
                    uint32_t a3 = spr[8 * STU + kb + 4];
                    #pragma unroll
                    for (int j = 0; j < 2; j++)
                        MMA_TF32(acc[mt][j][0], acc[mt][j][1], acc[mt][j][2], acc[mt][j][3],
                                 a0, a1, a2, a3, b0[j], b1[j]);
                }
            }

            // epilogue: out = z(regs) + delta
            #pragma unroll
            for (int mt = 0; mt < 2; mt++) {
                #pragma unroll
                for (int half = 0; half < 2; half++) {
                    int rr = wm * 32 + mt * 16 + gid + half * 8;
                    if (rr < nc) {
                        float* orow = out + (size_t)gsr[mt][half] * HH + h0;
                        #pragma unroll
                        for (int j = 0; j < 2; j++) {
                            int col = wn * 16 + j * 8 + 2 * tig;
                            float2 zz = zpre[mt][half][j];
                            *(float2*)&orow[col] =
                                make_float2(zz.x + acc[mt][j][half * 2 + 0],
                                            zz.y + acc[mt][j][half * 2 + 1]);
                        }
                    }
                }
            }
        }
    }
}

// ---------------------------------------------------------------------------
extern "C" void kernel_launch(void* const* d_in, const int* in_sizes, int n_in,
                              void* d_out, int out_size) {
    const float* z   = (const float*)d_in[0];
    const int*   ids = (const int*)  d_in[1];
    const float* u   = (const float*)d_in[2];
    const float* v   = (const float*)d_in[3];
    float*       out = (float*)d_out;

    const int fused_smem = (MT * STZ + KCH * STB) * 4;   // 35.8 KB (max of both roles)
    cudaFuncSetAttribute(fused_kernel, cudaFuncAttributeMaxDynamicSharedMemorySize, fused_smem);

    setup_kernel<<<1, 256>>>(ids);
    fused_kernel<<<PROJ_BLOCKS + OUT_BLOCKS, TPB, fused_smem>>>(z, v, u, out);
}

// round 12
// speedup vs baseline: 1.4825x; 1.0338x over previous
#include <cuda_runtime.h>
#include <cstdint>

// Problem constants
#define BB   2048
#define HH   2048
#define RNK  64
#define LL   32

#define NKG  32          // split-K groups for GEMM1 (k per block = 64)
#define KCH  64
#define MT   64          // M tile (samples)
#define HT   64          // h tile for GEMM2
#define TPB  256         // 8 warps everywhere
#define STZ  68          // sample-major tiles stride (68 mod 32 == 4)
#define STB  72          // k-major v tile stride     (72 mod 32 == 8)
#define STU  68          // n-major u/proj stride     (68 mod 32 == 4)

#define PROJ_BLOCKS (NKG * LL)        // 1024
#define OUT_BLOCKS  ((HH / HT) * LL)  // 1024
#define GRID_TOTAL  (1 + PROJ_BLOCKS + OUT_BLOCKS)  // 2049

// Scratch (device globals — no allocations allowed).
// Synchronization state is MONOTONIC across graph replays (epoch-versioned):
// nothing is ever reset, so no separate zeroing launch is needed.
__device__ int    g_offsets[LL + 1];
__device__ int    g_sorted[BB];
__device__ float  g_partial[(size_t)NKG * BB * RNK];   // 16 MB, by sorted pos
__device__ float  g_proj[(size_t)BB * RNK];            // by sorted pos
__device__ int    g_epoch    = 0;
__device__ int    g_sortflag = 0;      // holds epoch when sort complete
__device__ int    g_done[LL]  = {};    // monotonic: (E+1)*NKG when layer proj done
__device__ int    g_rdone[LL] = {};    // monotonic: (E+1)*NKG when layer reduce done
__device__ int    g_flag[LL]  = {};    // holds epoch when layer proj+reduce done
__device__ int    g_allcnt   = 0;      // monotonic: (E+1)*GRID_TOTAL at replay end

#define MMA_TF32(c0,c1,c2,c3,a0,a1,a2,a3,b0,b1)                         \
    asm("mma.sync.aligned.m16n8k8.row.col.f32.tf32.tf32.f32 "           \
        "{%0,%1,%2,%3}, {%4,%5,%6,%7}, {%8,%9}, {%0,%1,%2,%3};"         \
        : "+f"(c0), "+f"(c1), "+f"(c2), "+f"(c3)                        \
        : "r"(a0), "r"(a1), "r"(a2), "r"(a3), "r"(b0), "r"(b1))

__device__ __forceinline__ void cpa16(uint32_t dst, const void* src, uint32_t sz) {
    asm volatile("cp.async.cg.shared.global [%0], [%1], 16, %2;"
                 :: "r"(dst), "l"(src), "r"(sz));
}
__device__ __forceinline__ void cpa_commit() { asm volatile("cp.async.commit_group;"); }
__device__ __forceinline__ void cpa_wait0()  { asm volatile("cp.async.wait_group 0;"); }

// ---------------------------------------------------------------------------
// Single fused kernel:
//   bid 0                : sort block (stable counting sort -> sortflag)
//   bid in [1, 1025)     : proj block (l = (bid-1)/32, kg = (bid-1)%32)
//   bid in [1025, 2049)  : out block  (l = (bid-1025)/32, hb = (bid-1025)%32)
// Waiter bids are strictly greater than their dependency bids -> deadlock-free.
// ---------------------------------------------------------------------------
__global__ __launch_bounds__(TPB, 3) void fused_kernel(const float* __restrict__ z,
                                                       const int*   __restrict__ ids,
                                                       const float* __restrict__ v,
                                                       const float* __restrict__ u,
                                                       float* __restrict__ out) {
    extern __shared__ __align__(16) uint32_t smem[];
    __shared__ int s_E;
    __shared__ int s_tmp;

    int t = threadIdx.x, lane = t & 31, w = t >> 5;
    int gid = lane >> 2, tig = lane & 3;
    int wm = w & 1, wn = w >> 1;           // 8 warps: m32 x n16
    int bid = blockIdx.x;

    if (t == 0) s_E = *(volatile int*)&g_epoch;
    __syncthreads();
    const int E = s_E;

    if (bid == 0) {
        // ================= SORT =================
        int* A = (int*)smem;               // [LL*256] 32 KB
        int* S = A + LL * 256;             // [256]
        #pragma unroll
        for (int l = 0; l < LL; l++) A[l * 256 + t] = 0;
        int seg = t * (BB / 256);
        #pragma unroll
        for (int i = 0; i < BB / 256; i++) {
            int lid = ids[seg + i];
            A[lid * 256 + t]++;
        }
        __syncthreads();
        int base = t * 32;
        int sum = 0;
        #pragma unroll
        for (int j = 0; j < 32; j++) { int x = A[base + j]; A[base + j] = sum; sum += x; }
        S[t] = sum;
        int mysum = sum;
        __syncthreads();
        for (int d = 1; d < 256; d <<= 1) {
            int add = (t >= d) ? S[t - d] : 0;
            __syncthreads();
            S[t] += add;
            __syncthreads();
        }
        int excl = S[t] - mysum;
        #pragma unroll
        for (int j = 0; j < 32; j++) A[base + j] += excl;
        __syncthreads();
        if (t < LL) g_offsets[t] = A[t * 256];
        if (t == 0) g_offsets[LL] = BB;
        #pragma unroll
        for (int i = 0; i < BB / 256; i++) {
            int s = seg + i;
            int lid = ids[s];
            int p = A[lid * 256 + t];
            A[lid * 256 + t] = p + 1;
            g_sorted[p] = s;
        }
        __threadfence();
        __syncthreads();
        if (t == 0) atomicExch(&g_sortflag, E + 1);
    } else if (bid <= PROJ_BLOCKS) {
        // ================= PROJ =================
        int pb = bid - 1;
        int l = pb >> 5, kg = pb & 31;
        int k0 = kg * KCH;
        uint32_t* sz = smem;               // [MT][STZ]  17.4 KB
        uint32_t* sv = smem + MT * STZ;    // [KCH][STB] 18.4 KB
        uint32_t sz_b = (uint32_t)__cvta_generic_to_shared(sz);
        uint32_t sv_b = (uint32_t)__cvta_generic_to_shared(sv);

        // stage v tile FIRST (independent of the sort), overlaps the spin
        #pragma unroll
        for (int i = 0; i < (KCH * 16) / TPB; i++) {    // 4 iters
            int idx = t + i * TPB;
            int row = idx >> 4, c4 = idx & 15;
            cpa16(sv_b + (row * STB + c4 * 4) * 4,
                  v + ((size_t)l * HH + k0 + row) * RNK + c4 * 4, 16);
        }
        cpa_commit();

        // wait for sort
        if (t == 0) { while (atomicAdd(&g_sortflag, 0) < E + 1) __nanosleep(64); }
        __syncthreads();
        __threadfence();

        int off = g_offsets[l];
        int cnt = g_offsets[l + 1] - off;

        for (int m0 = 0; m0 < cnt; m0 += MT) {
            int nc = min(MT, cnt - m0);
            if (m0 > 0) __syncthreads();   // z smem free from previous iteration
            #pragma unroll
            for (int i = 0; i < (MT * 16) / TPB; i++) {     // 4 iters
                int idx = t + i * TPB;
                int row = idx >> 4, c4 = idx & 15;
                const float* src = z;
                uint32_t szb = 0;
                if (row < nc) {
                    int gs = g_sorted[off + m0 + row];
                    src = z + (size_t)gs * HH + k0 + c4 * 4;
                    szb = 16;
                }
                cpa16(sz_b + (row * STZ + c4 * 4) * 4, src, szb);
            }
            cpa_commit();
            cpa_wait0();                    // first iter also covers v
            __syncthreads();

            float acc[2][2][4];
            #pragma unroll
            for (int mt = 0; mt < 2; mt++)
                #pragma unroll
                for (int j = 0; j < 2; j++)
                    #pragma unroll
                    for (int q = 0; q < 4; q++) acc[mt][j][q] = 0.0f;

            #pragma unroll
            for (int ks = 0; ks < KCH / 8; ks++) {          // 8 iters
                int kb = ks * 8 + tig;
                uint32_t b0[2], b1[2];
                #pragma unroll
                for (int j = 0; j < 2; j++) {
                    int n = wn * 16 + j * 8 + gid;
                    b0[j] = sv[kb * STB + n];
                    b1[j] = sv[(kb + 4) * STB + n];
                }
                #pragma unroll
                for (int mt = 0; mt < 2; mt++) {
                    const uint32_t* zr = sz + (wm * 32 + mt * 16 + gid) * STZ;
                    uint32_t a0 = zr[kb];
                    uint32_t a1 = zr[8 * STZ + kb];
                    uint32_t a2 = zr[kb + 4];
                    uint32_t a3 = zr[8 * STZ + kb + 4];
                    #pragma unroll
                    for (int j = 0; j < 2; j++)
                        MMA_TF32(acc[mt][j][0], acc[mt][j][1], acc[mt][j][2], acc[mt][j][3],
                                 a0, a1, a2, a3, b0[j], b1[j]);
                }
            }

            float* pb2 = g_partial + (size_t)kg * BB * RNK;
            #pragma unroll
            for (int mt = 0; mt < 2; mt++) {
                int rbase = wm * 32 + mt * 16 + gid;
                #pragma unroll
                for (int j = 0; j < 2; j++) {
                    int col = wn * 16 + j * 8 + 2 * tig;
                    if (rbase < nc)
                        *(float2*)&pb2[(size_t)(off + m0 + rbase) * RNK + col] =
                            make_float2(acc[mt][j][0], acc[mt][j][1]);
                    if (rbase + 8 < nc)
                        *(float2*)&pb2[(size_t)(off + m0 + rbase + 8) * RNK + col] =
                            make_float2(acc[mt][j][2], acc[mt][j][3]);
                }
            }
        }

        // all NKG blocks of this layer rendezvous, then reduce cooperatively
        __threadfence();
        __syncthreads();
        if (t == 0) {
            atomicAdd(&g_done[l], 1);
            while (atomicAdd(&g_done[l], 0) < (E + 1) * NKG) __nanosleep(64);
        }
        __syncthreads();
        __threadfence();

        {
            const int n4 = cnt * (RNK / 4);
            const int base4 = off * (RNK / 4);
            const float4* pp = (const float4*)g_partial;
            const int stride4 = BB * RNK / 4;
            for (int i = kg * TPB + t; i < n4; i += NKG * TPB) {
                float4 s = __ldcg(pp + base4 + i);
                #pragma unroll
                for (int kc = 1; kc < NKG; kc++) {
                    float4 q = __ldcg(pp + (size_t)kc * stride4 + base4 + i);
                    s.x += q.x; s.y += q.y; s.z += q.z; s.w += q.w;
                }
                ((float4*)g_proj)[base4 + i] = s;
            }
        }
        __threadfence();
        __syncthreads();
        if (t == 0) {
            int r = atomicAdd(&g_rdone[l], 1);
            if (r == (E + 1) * NKG - 1) atomicExch(&g_flag[l], E + 1);
        }
    } else {
        // ================= OUT =================
        int ob = bid - 1 - PROJ_BLOCKS;
        int l = ob >> 5, hb = ob & 31;
        int h0 = hb * HT;
        uint32_t* su = smem;               // [HT][STU]  17.4 KB
        uint32_t* sp = smem + HT * STU;    // [MT][STU]  17.4 KB
        uint32_t su_b = (uint32_t)__cvta_generic_to_shared(su);
        uint32_t sp_b = (uint32_t)__cvta_generic_to_shared(sp);

        // stage u tile (independent of everything), overlaps the spin
        #pragma unroll
        for (int i = 0; i < (HT * 16) / TPB; i++) {         // 4 iters
            int idxx = t + i * TPB;
            int row = idxx >> 4, c4 = idxx & 15;
            cpa16(su_b + (row * STU + c4 * 4) * 4,
                  u + ((size_t)l * HH + h0 + row) * RNK + c4 * 4, 16);
        }
        cpa_commit();

        // wait for this layer's proj+reduce (implies sort done)
        if (t == 0) { while (atomicAdd(&g_flag[l], 0) < E + 1) __nanosleep(128); }
        __syncthreads();
        __threadfence();

        int off = g_offsets[l];
        int cnt = g_offsets[l + 1] - off;

        for (int m0 = 0; m0 < cnt; m0 += MT) {
            int nc = min(MT, cnt - m0);
            if (m0 > 0) __syncthreads();
            #pragma unroll
            for (int i = 0; i < (MT * 16) / TPB; i++) {     // 4 iters
                int idxx = t + i * TPB;
                int row = idxx >> 4, c4 = idxx & 15;
                const float* src = g_proj;
                uint32_t szb = 0;
                if (row < nc) {
                    src = g_proj + (size_t)(off + m0 + row) * RNK + c4 * 4;
                    szb = 16;
                }
                cpa16(sp_b + (row * STU + c4 * 4) * 4, src, szb);
            }
            cpa_commit();
            cpa_wait0();   // also covers u on first iteration
            __syncthreads();

            // prefetch epilogue z into registers (overlaps MMA)
            int    gsr[2][2];
            float2 zpre[2][2][2];
            #pragma unroll
            for (int mt = 0; mt < 2; mt++)
                #pragma unroll
                for (int half = 0; half < 2; half++) {
                    int rr = wm * 32 + mt * 16 + gid + half * 8;
                    int rid = (rr < nc) ? rr : 0;
                    int gs = g_sorted[off + m0 + rid];
                    gsr[mt][half] = gs;
                    const float* zrow = z + (size_t)gs * HH + h0;
                    #pragma unroll
                    for (int j = 0; j < 2; j++)
                        zpre[mt][half][j] = *(const float2*)&zrow[wn * 16 + j * 8 + 2 * tig];
                }

            float acc[2][2][4];
            #pragma unroll
            for (int mt = 0; mt < 2; mt++)
                #pragma unroll
                for (int j = 0; j < 2; j++)
                    #pragma unroll
                    for (int q = 0; q < 4; q++) acc[mt][j][q] = 0.0f;

            #pragma unroll
            for (int ks = 0; ks < 8; ks++) {
                int kb = ks * 8 + tig;
                uint32_t b0[2], b1[2];
                #pragma unroll
                for (int j = 0; j < 2; j++) {
                    int n = wn * 16 + j * 8 + gid;
                    b0[j] = su[n * STU + kb];
                    b1[j] = su[n * STU + kb + 4];
                }
                #pragma unroll
                for (int mt = 0; mt < 2; mt++) {
                    const uint32_t* spr = sp + (wm * 32 + mt * 16 + gid) * STU;
                    uint32_t a0 = spr[kb];
                    uint32_t a1 = spr[8 * STU + kb];
                    uint32_t a2 = spr[kb + 4];
                    uint32_t a3 = spr[8 * STU + kb + 4];
                    #pragma unroll
                    for (int j = 0; j < 2; j++)
                        MMA_TF32(acc[mt][j][0], acc[mt][j][1], acc[mt][j][2], acc[mt][j][3],
                                 a0, a1, a2, a3, b0[j], b1[j]);
                }
            }

            // epilogue: out = z(regs) + delta
            #pragma unroll
            for (int mt = 0; mt < 2; mt++) {
                #pragma unroll
                for (int half = 0; half < 2; half++) {
                    int rr = wm * 32 + mt * 16 + gid + half * 8;
                    if (rr < nc) {
                        float* orow = out + (size_t)gsr[mt][half] * HH + h0;
                        #pragma unroll
                        for (int j = 0; j < 2; j++) {
                            int col = wn * 16 + j * 8 + 2 * tig;
                            float2 zz = zpre[mt][half][j];
                            *(float2*)&orow[col] =
                                make_float2(zz.x + acc[mt][j][half * 2 + 0],
                                            zz.y + acc[mt][j][half * 2 + 1]);
                        }
                    }
                }
            }
        }
    }

    // replay epilogue: last block of this replay advances the epoch
    __syncthreads();
    if (t == 0) {
        int r = atomicAdd(&g_allcnt, 1);
        if (r == (E + 1) * GRID_TOTAL - 1) atomicExch(&g_epoch, E + 1);
    }
}

// ---------------------------------------------------------------------------
extern "C" void kernel_launch(void* const* d_in, const int* in_sizes, int n_in,
                              void* d_out, int out_size) {
    const float* z   = (const float*)d_in[0];
    const int*   ids = (const int*)  d_in[1];
    const float* u   = (const float*)d_in[2];
    const float* v   = (const float*)d_in[3];
    float*       out = (float*)d_out;

    const int fused_smem = (MT * STZ + KCH * STB) * 4;   // 35.8 KB (covers sort's 33 KB)
    cudaFuncSetAttribute(fused_kernel, cudaFuncAttributeMaxDynamicSharedMemorySize, fused_smem);

    fused_kernel<<<GRID_TOTAL, TPB, fused_smem>>>(z, ids, v, u, out);
}

// round 13
// speedup vs baseline: 1.6115x; 1.0870x over previous
#include <cuda_runtime.h>
#include <cstdint>

// Problem constants
#define BB   2048
#define HH   2048
#define RNK  64
#define LL   32

#define NKG  32          // split-K groups for GEMM1 (k per block = 64)
#define KCH  64
#define MT   64          // M tile (samples)
#define HT   64          // h tile for GEMM2
#define TPB  256         // 8 warps everywhere
#define STZ  68          // sample-major tiles stride (68 mod 32 == 4)
#define STB  72          // k-major v tile stride     (72 mod 32 == 8)
#define STU  68          // n-major u/proj stride     (68 mod 32 == 4)

#define PROJ_BLOCKS (NKG * LL)        // 1024
#define OUT_BLOCKS  ((HH / HT) * LL)  // 1024
#define GRID_TOTAL  (1 + PROJ_BLOCKS + OUT_BLOCKS)  // 2049

// Scratch (device globals — no allocations allowed).
// Synchronization state is MONOTONIC across graph replays (epoch-versioned).
__device__ int    g_offsets[LL + 1];
__device__ int    g_sorted[BB];
__device__ float  g_partial[(size_t)NKG * BB * RNK];   // 16 MB, by sorted pos
__device__ float  g_proj[(size_t)BB * RNK];            // by sorted pos
__device__ int    g_epoch    = 0;
__device__ int    g_sortflag = 0;      // holds epoch when sort complete
__device__ int    g_done[LL]  = {};    // monotonic: (E+1)*NKG when layer proj done
__device__ int    g_rdone[LL] = {};    // monotonic
__device__ int    g_flag[LL]  = {};    // holds epoch when layer proj+reduce done
__device__ int    g_allcnt   = 0;      // monotonic

#define MMA_TF32(c0,c1,c2,c3,a0,a1,a2,a3,b0,b1)                         \
    asm("mma.sync.aligned.m16n8k8.row.col.f32.tf32.tf32.f32 "           \
        "{%0,%1,%2,%3}, {%4,%5,%6,%7}, {%8,%9}, {%0,%1,%2,%3};"         \
        : "+f"(c0), "+f"(c1), "+f"(c2), "+f"(c3)                        \
        : "r"(a0), "r"(a1), "r"(a2), "r"(a3), "r"(b0), "r"(b1))

__device__ __forceinline__ void cpa16(uint32_t dst, const void* src, uint32_t sz) {
    asm volatile("cp.async.cg.shared.global [%0], [%1], 16, %2;"
                 :: "r"(dst), "l"(src), "r"(sz));
}
__device__ __forceinline__ void cpa_commit() { asm volatile("cp.async.commit_group;"); }
__device__ __forceinline__ void cpa_wait0()  { asm volatile("cp.async.wait_group 0;"); }

// Low-contention spin: plain L2 load (no RMW), growing backoff.
__device__ __forceinline__ void spin_ge(const int* addr, int target) {
    unsigned ns = 64;
    while (__ldcg(addr) < target) {
        __nanosleep(ns);
        if (ns < 1024) ns <<= 1;
    }
}

// ---------------------------------------------------------------------------
// Single fused kernel:
//   bid 0               : sort block
//   bid in [1, 1025)    : proj block (l = (bid-1)/32, kg = (bid-1)%32)
//   bid in [1025, 2049) : out block  (l = (bid-1025)/32, hb = (bid-1025)%32)
// ---------------------------------------------------------------------------
__global__ __launch_bounds__(TPB, 3) void fused_kernel(const float* __restrict__ z,
                                                       const int*   __restrict__ ids,
                                                       const float* __restrict__ v,
                                                       const float* __restrict__ u,
                                                       float* __restrict__ out) {
    extern __shared__ __align__(16) uint32_t smem[];
    __shared__ int s_E;

    int t = threadIdx.x, lane = t & 31, w = t >> 5;
    int gid = lane >> 2, tig = lane & 3;
    int wm = w & 1, wn = w >> 1;           // 8 warps: m32 x n16
    int bid = blockIdx.x;

    if (t == 0) s_E = __ldcg(&g_epoch);
    __syncthreads();
    const int E = s_E;

    if (bid == 0) {
        // ================= SORT =================
        int* A = (int*)smem;               // [LL*256] 32 KB
        int* S = A + LL * 256;             // [256]
        #pragma unroll
        for (int l = 0; l < LL; l++) A[l * 256 + t] = 0;
        int seg = t * (BB / 256);
        #pragma unroll
        for (int i = 0; i < BB / 256; i++) {
            int lid = ids[seg + i];
            A[lid * 256 + t]++;
        }
        __syncthreads();
        int base = t * 32;
        int sum = 0;
        #pragma unroll
        for (int j = 0; j < 32; j++) { int x = A[base + j]; A[base + j] = sum; sum += x; }
        S[t] = sum;
        int mysum = sum;
        __syncthreads();
        for (int d = 1; d < 256; d <<= 1) {
            int add = (t >= d) ? S[t - d] : 0;
            __syncthreads();
            S[t] += add;
            __syncthreads();
        }
        int excl = S[t] - mysum;
        #pragma unroll
        for (int j = 0; j < 32; j++) A[base + j] += excl;
        __syncthreads();
        if (t < LL) g_offsets[t] = A[t * 256];
        if (t == 0) g_offsets[LL] = BB;
        #pragma unroll
        for (int i = 0; i < BB / 256; i++) {
            int s = seg + i;
            int lid = ids[s];
            int p = A[lid * 256 + t];
            A[lid * 256 + t] = p + 1;
            g_sorted[p] = s;
        }
        __threadfence();
        __syncthreads();
        if (t == 0) atomicExch(&g_sortflag, E + 1);
    } else if (bid <= PROJ_BLOCKS) {
        // ================= PROJ =================
        int pb = bid - 1;
        int l = pb >> 5, kg = pb & 31;
        int k0 = kg * KCH;
        uint32_t* sz = smem;               // [MT][STZ]  17.4 KB
        uint32_t* sv = smem + MT * STZ;    // [KCH][STB] 18.4 KB
        uint32_t sz_b = (uint32_t)__cvta_generic_to_shared(sz);
        uint32_t sv_b = (uint32_t)__cvta_generic_to_shared(sv);

        // stage v tile FIRST (independent of the sort), overlaps the spin
        #pragma unroll
        for (int i = 0; i < (KCH * 16) / TPB; i++) {    // 4 iters
            int idx = t + i * TPB;
            int row = idx >> 4, c4 = idx & 15;
            cpa16(sv_b + (row * STB + c4 * 4) * 4,
                  v + ((size_t)l * HH + k0 + row) * RNK + c4 * 4, 16);
        }
        cpa_commit();

        // wait for sort (load-poll, no RMW)
        if (t == 0) spin_ge(&g_sortflag, E + 1);
        __syncthreads();
        __threadfence();

        int off = g_offsets[l];
        int cnt = g_offsets[l + 1] - off;

        for (int m0 = 0; m0 < cnt; m0 += MT) {
            int nc = min(MT, cnt - m0);
            if (m0 > 0) __syncthreads();   // z smem free from previous iteration
            #pragma unroll
            for (int i = 0; i < (MT * 16) / TPB; i++) {     // 4 iters
                int idx = t + i * TPB;
                int row = idx >> 4, c4 = idx & 15;
                const float* src = z;
                uint32_t szb = 0;
                if (row < nc) {
                    int gs = g_sorted[off + m0 + row];
                    src = z + (size_t)gs * HH + k0 + c4 * 4;
                    szb = 16;
                }
                cpa16(sz_b + (row * STZ + c4 * 4) * 4, src, szb);
            }
            cpa_commit();
            cpa_wait0();                    // first iter also covers v
            __syncthreads();

            float acc[2][2][4];
            #pragma unroll
            for (int mt = 0; mt < 2; mt++)
                #pragma unroll
                for (int j = 0; j < 2; j++)
                    #pragma unroll
                    for (int q = 0; q < 4; q++) acc[mt][j][q] = 0.0f;

            #pragma unroll
            for (int ks = 0; ks < KCH / 8; ks++) {          // 8 iters
                int kb = ks * 8 + tig;
                uint32_t b0[2], b1[2];
                #pragma unroll
                for (int j = 0; j < 2; j++) {
                    int n = wn * 16 + j * 8 + gid;
                    b0[j] = sv[kb * STB + n];
                    b1[j] = sv[(kb + 4) * STB + n];
                }
                #pragma unroll
                for (int mt = 0; mt < 2; mt++) {
                    const uint32_t* zr = sz + (wm * 32 + mt * 16 + gid) * STZ;
                    uint32_t a0 = zr[kb];
                    uint32_t a1 = zr[8 * STZ + kb];
                    uint32_t a2 = zr[kb + 4];
                    uint32_t a3 = zr[8 * STZ + kb + 4];
                    #pragma unroll
                    for (int j = 0; j < 2; j++)
                        MMA_TF32(acc[mt][j][0], acc[mt][j][1], acc[mt][j][2], acc[mt][j][3],
                                 a0, a1, a2, a3, b0[j], b1[j]);
                }
            }

            float* pb2 = g_partial + (size_t)kg * BB * RNK;
            #pragma unroll
            for (int mt = 0; mt < 2; mt++) {
                int rbase = wm * 32 + mt * 16 + gid;
                #pragma unroll
                for (int j = 0; j < 2; j++) {
                    int col = wn * 16 + j * 8 + 2 * tig;
                    if (rbase < nc)
                        *(float2*)&pb2[(size_t)(off + m0 + rbase) * RNK + col] =
                            make_float2(acc[mt][j][0], acc[mt][j][1]);
                    if (rbase + 8 < nc)
                        *(float2*)&pb2[(size_t)(off + m0 + rbase + 8) * RNK + col] =
                            make_float2(acc[mt][j][2], acc[mt][j][3]);
                }
            }
        }

        // all NKG blocks of this layer rendezvous (single atomic + load-poll)
        __threadfence();
        __syncthreads();
        if (t == 0) {
            atomicAdd(&g_done[l], 1);
            spin_ge(&g_done[l], (E + 1) * NKG);
        }
        __syncthreads();
        __threadfence();

        {
            const int n4 = cnt * (RNK / 4);
            const int base4 = off * (RNK / 4);
            const float4* pp = (const float4*)g_partial;
            const int stride4 = BB * RNK / 4;
            for (int i = kg * TPB + t; i < n4; i += NKG * TPB) {
                float4 s = __ldcg(pp + base4 + i);
                #pragma unroll
                for (int kc = 1; kc < NKG; kc++) {
                    float4 q = __ldcg(pp + (size_t)kc * stride4 + base4 + i);
                    s.x += q.x; s.y += q.y; s.z += q.z; s.w += q.w;
                }
                ((float4*)g_proj)[base4 + i] = s;
            }
        }
        __threadfence();
        __syncthreads();
        if (t == 0) {
            int r = atomicAdd(&g_rdone[l], 1);
            if (r == (E + 1) * NKG - 1) atomicExch(&g_flag[l], E + 1);
        }
    } else {
        // ================= OUT =================
        int ob = bid - 1 - PROJ_BLOCKS;
        int l = ob >> 5, hb = ob & 31;
        int h0 = hb * HT;
        uint32_t* su = smem;               // [HT][STU]  17.4 KB
        uint32_t* sp = smem + HT * STU;    // [MT][STU]  17.4 KB
        uint32_t su_b = (uint32_t)__cvta_generic_to_shared(su);
        uint32_t sp_b = (uint32_t)__cvta_generic_to_shared(sp);

        // stage u tile (independent of everything), overlaps the spin
        #pragma unroll
        for (int i = 0; i < (HT * 16) / TPB; i++) {         // 4 iters
            int idxx = t + i * TPB;
            int row = idxx >> 4, c4 = idxx & 15;
            cpa16(su_b + (row * STU + c4 * 4) * 4,
                  u + ((size_t)l * HH + h0 + row) * RNK + c4 * 4, 16);
        }
        cpa_commit();

        // wait for this layer's proj+reduce (load-poll; implies sort done)
        if (t == 0) spin_ge(&g_flag[l], E + 1);
        __syncthreads();
        __threadfence();

        int off = g_offsets[l];
        int cnt = g_offsets[l + 1] - off;

        for (int m0 = 0; m0 < cnt; m0 += MT) {
            int nc = min(MT, cnt - m0);
            if (m0 > 0) __syncthreads();
            #pragma unroll
            for (int i = 0; i < (MT * 16) / TPB; i++) {     // 4 iters
                int idxx = t + i * TPB;
                int row = idxx >> 4, c4 = idxx & 15;
                const float* src = g_proj;
                uint32_t szb = 0;
                if (row < nc) {
                    src = g_proj + (size_t)(off + m0 + row) * RNK + c4 * 4;
                    szb = 16;
                }
                cpa16(sp_b + (row * STU + c4 * 4) * 4, src, szb);
            }
            cpa_commit();

            // prefetch epilogue z into registers BEFORE the wait — its DRAM
            // latency overlaps the cp.async completion instead of following it
            int    gsr[2][2];
            float2 zpre[2][2][2];
            #pragma unroll
            for (int mt = 0; mt < 2; mt++)
                #pragma unroll
                for (int half = 0; half < 2; half++) {
                    int rr = wm * 32 + mt * 16 + gid + half * 8;
                    int rid = (rr < nc) ? rr : 0;
                    int gs = g_sorted[off + m0 + rid];
                    gsr[mt][half] = gs;
                    const float* zrow = z + (size_t)gs * HH + h0;
                    #pragma unroll
                    for (int j = 0; j < 2; j++)
                        zpre[mt][half][j] = *(const float2*)&zrow[wn * 16 + j * 8 + 2 * tig];
                }

            cpa_wait0();   // also covers u on first iteration
            __syncthreads();

            float acc[2][2][4];
            #pragma unroll
            for (int mt = 0; mt < 2; mt++)
                #pragma unroll
                for (int j = 0; j < 2; j++)
                    #pragma unroll
                    for (int q = 0; q < 4; q++) acc[mt][j][q] = 0.0f;

            #pragma unroll
            for (int ks = 0; ks < 8; ks++) {
                int kb = ks * 8 + tig;
                uint32_t b0[2], b1[2];
                #pragma unroll
                for (int j = 0; j < 2; j++) {
                    int n = wn * 16 + j * 8 + gid;
                    b0[j] = su[n * STU + kb];
                    b1[j] = su[n * STU + kb + 4];
                }
                #pragma unroll
                for (int mt = 0; mt < 2; mt++) {
                    const uint32_t* spr = sp + (wm * 32 + mt * 16 + gid) * STU;
                    uint32_t a0 = spr[kb];
                    uint32_t a1 = spr[8 * STU + kb];
                    uint32_t a2 = spr[kb + 4];
                    uint32_t a3 = spr[8 * STU + kb + 4];
                    #pragma unroll
                    for (int j = 0; j < 2; j++)
                        MMA_TF32(acc[mt][j][0], acc[mt][j][1], acc[mt][j][2], acc[mt][j][3],
                                 a0, a1, a2, a3, b0[j], b1[j]);
                }
            }

            // epilogue: out = z(regs) + delta
            #pragma unroll
            for (int mt = 0; mt < 2; mt++) {
                #pragma unroll
                for (int half = 0; half < 2; half++) {
                    int rr = wm * 32 + mt * 16 + gid + half * 8;
                    if (rr < nc) {
                        float* orow = out + (size_t)gsr[mt][half] * HH + h0;
                        #pragma unroll
                        for (int j = 0; j < 2; j++) {
                            int col = wn * 16 + j * 8 + 2 * tig;
                            float2 zz = zpre[mt][half][j];
                            *(float2*)&orow[col] =
                                make_float2(zz.x + acc[mt][j][half * 2 + 0],
                                            zz.y + acc[mt][j][half * 2 + 1]);
                        }
                    }
                }
            }
        }
    }

    // replay epilogue: last block of this replay advances the epoch
    __syncthreads();
    if (t == 0) {
        int r = atomicAdd(&g_allcnt, 1);
        if (r == (E + 1) * GRID_TOTAL - 1) atomicExch(&g_epoch, E + 1);
    }
}

// ---------------------------------------------------------------------------
extern "C" void kernel_launch(void* const* d_in, const int* in_sizes, int n_in,
                              void* d_out, int out_size) {
    const float* z   = (const float*)d_in[0];
    const int*   ids = (const int*)  d_in[1];
    const float* u   = (const float*)d_in[2];
    const float* v   = (const float*)d_in[3];
    float*       out = (float*)d_out;

    const int fused_smem = (MT * STZ + KCH * STB) * 4;   // 35.8 KB (covers sort's 33 KB)
    cudaFuncSetAttribute(fused_kernel, cudaFuncAttributeMaxDynamicSharedMemorySize, fused_smem);

    fused_kernel<<<GRID_TOTAL, TPB, fused_smem>>>(z, ids, v, u, out);
}